// round 13
// baseline (speedup 1.0000x reference)
#include <cuda_runtime.h>
#include <cuda_fp16.h>
#include <math.h>

#define NN 100000
#define DD 64
#define EE 1600000
#define ETOT (EE + NN)
#define NB_SCAN 391   // ceil(NN/256)

// ---- scratch ----
__device__ __half g_h16[NN * DD];   // transformed features (payload, fp16)
__device__ __half g_e16[NN * DD];   // emb in fp16 (GEMM input, layer 0)
__device__ __half g_x1h[NN * DD];   // layer-1 output, fp16
__device__ __half g_x2h[NN * DD];   // layer-2 output, fp16
__device__ float  g_es[NN];
__device__ float  g_ed[NN];
__device__ uint2  g_sw[ETOT];       // per-edge (src, softmax weight)
__device__ int    g_counts[NN];
__device__ int    g_rowptr[NN + 1];
__device__ int    g_cursor[NN];
__device__ int2   g_csrd[ETOT];     // (src, dst) per CSR slot
__device__ int    g_bsum[NB_SCAN];
__device__ unsigned g_gmaxu[3];

// monotone float <-> orderable uint
__device__ __forceinline__ unsigned fenc(float f) {
    unsigned b = __float_as_uint(f);
    return (b & 0x80000000u) ? ~b : (b | 0x80000000u);
}
__device__ __forceinline__ float fdec(unsigned e) {
    return __uint_as_float((e & 0x80000000u) ? (e ^ 0x80000000u) : ~e);
}
__device__ __forceinline__ unsigned sptr(const void* p) {
    return (unsigned)__cvta_generic_to_shared(p);
}

// ---- init: emb -> fp16, counts = 1 (self loop), gmax reset ----
__global__ void k_emb16(const float4* __restrict__ emb4) {
    int i = blockIdx.x * blockDim.x + threadIdx.x;
    if (i < NN * DD / 4) {
        float4 v = emb4[i];
        __half2 lo = __float22half2_rn(make_float2(v.x, v.y));
        __half2 hi = __float22half2_rn(make_float2(v.z, v.w));
        ((uint2*)g_e16)[i] = make_uint2(*(unsigned*)&lo, *(unsigned*)&hi);
    }
    if (i < NN) g_counts[i] = 1;
    if (i < 3) g_gmaxu[i] = 0u;
}

// ---- in-degree count ----
__global__ void k_count(const int* __restrict__ dsts) {
    int i = blockIdx.x * blockDim.x + threadIdx.x;
    if (i >= EE / 4) return;
    int4 d = ((const int4*)dsts)[i];
    atomicAdd(&g_counts[d.x], 1);
    atomicAdd(&g_counts[d.y], 1);
    atomicAdd(&g_counts[d.z], 1);
    atomicAdd(&g_counts[d.w], 1);
}

// ---- block sums of counts ----
__global__ void __launch_bounds__(256) k_bsum() {
    __shared__ int sh[256];
    int t = threadIdx.x;
    int i = blockIdx.x * 256 + t;
    sh[t] = (i < NN) ? g_counts[i] : 0;
    __syncthreads();
    for (int o = 128; o > 0; o >>= 1) {
        if (t < o) sh[t] += sh[t + o];
        __syncthreads();
    }
    if (t == 0) g_bsum[blockIdx.x] = sh[0];
}

// ---- rowptr: per-block offset + local scan ----
__global__ void __launch_bounds__(256) k_fillptr() {
    __shared__ int sh[256];
    __shared__ int wsum[8];
    __shared__ int s_off;
    int t = threadIdx.x, b = blockIdx.x;
    int part = 0;
    for (int j = t; j < b; j += 256) part += g_bsum[j];
    sh[t] = part;
    __syncthreads();
    for (int o = 128; o > 0; o >>= 1) {
        if (t < o) sh[t] += sh[t + o];
        __syncthreads();
    }
    if (t == 0) s_off = sh[0];
    __syncthreads();

    int i = b * 256 + t;
    int c = (i < NN) ? g_counts[i] : 0;
    int lane = t & 31, w = t >> 5;
    int v = c;
#pragma unroll
    for (int o = 1; o < 32; o <<= 1) {
        int u = __shfl_up_sync(0xffffffffu, v, o);
        if (lane >= o) v += u;
    }
    if (lane == 31) wsum[w] = v;
    __syncthreads();
    if (t == 0) {
        int run = 0;
#pragma unroll
        for (int j = 0; j < 8; j++) { int tmp = wsum[j]; wsum[j] = run; run += tmp; }
    }
    __syncthreads();
    int excl = s_off + wsum[w] + v - c;
    if (i < NN) {
        g_rowptr[i] = excl;
        g_cursor[i] = excl;
        if (i == NN - 1) g_rowptr[NN] = excl + c;
    }
}

// ---- scatter (src,dst) into dst buckets (+ self loops), scalar ----
__global__ void k_fill(const int* __restrict__ srcs, const int* __restrict__ dsts) {
    int i = blockIdx.x * blockDim.x + threadIdx.x;
    if (i >= ETOT) return;
    int s, d;
    if (i < EE) { s = srcs[i]; d = dsts[i]; }
    else        { s = d = i - EE; }
    int pos = atomicAdd(&g_cursor[d], 1);
    g_csrd[pos] = make_int2(s, d);
}

// ---- HMMA helpers ----
__device__ __forceinline__ void mma16816(
    float& c0, float& c1, float& c2, float& c3,
    unsigned a0, unsigned a1, unsigned a2, unsigned a3,
    unsigned b0, unsigned b1)
{
    asm volatile(
        "mma.sync.aligned.m16n8k16.row.col.f32.f16.f16.f32 "
        "{%0,%1,%2,%3}, {%4,%5,%6,%7}, {%8,%9}, {%0,%1,%2,%3};"
        : "+f"(c0), "+f"(c1), "+f"(c2), "+f"(c3)
        : "r"(a0), "r"(a1), "r"(a2), "r"(a3), "r"(b0), "r"(b1));
}
__device__ __forceinline__ void ldsm4(
    unsigned& r0, unsigned& r1, unsigned& r2, unsigned& r3, unsigned addr)
{
    asm volatile(
        "ldmatrix.sync.aligned.m8n8.x4.shared.b16 {%0,%1,%2,%3}, [%4];"
        : "=r"(r0), "=r"(r1), "=r"(r2), "=r"(r3) : "r"(addr));
}

// ---- transform: h = x@W via HMMA; fp16 in/out; es/ed; fused block-max ----
#define XPAD 72
__global__ void __launch_bounds__(256) k_transform(
    int layer, const float* __restrict__ W,
    const float* __restrict__ a_s, const float* __restrict__ a_d)
{
    __shared__ __half Xh[128][XPAD];
    __shared__ __half Wn[64][XPAD];   // Wn[n][k] = W[k][n]
    __shared__ float ash[64];
    __shared__ float adh[64];
    __shared__ float smax[8];
    const __half* x = (layer == 0) ? g_e16 : (layer == 1 ? g_x1h : g_x2h);
    int tid = threadIdx.x;
    int rb = blockIdx.x * 128;

    const float4* Wg4 = (const float4*)W;
#pragma unroll
    for (int idx = tid; idx < 1024; idx += 256) {
        int k = idx >> 4, n4 = (idx & 15) << 2;
        float4 w = Wg4[idx];
        Wn[n4 + 0][k] = __float2half(w.x);
        Wn[n4 + 1][k] = __float2half(w.y);
        Wn[n4 + 2][k] = __float2half(w.z);
        Wn[n4 + 3][k] = __float2half(w.w);
    }
    if (tid < 64) { ash[tid] = a_s[tid]; adh[tid] = a_d[tid]; }

    const uint4* Xg = (const uint4*)x;
#pragma unroll
    for (int idx = tid; idx < 1024; idx += 256) {
        int r = idx >> 3, c8 = idx & 7;
        uint4 v = (rb + r < NN) ? Xg[(rb + r) * 8 + c8]
                                : make_uint4(0u, 0u, 0u, 0u);
        *(uint4*)&Xh[r][c8 * 8] = v;
    }
    __syncthreads();

    int warp = tid >> 5, lane = tid & 31;
    int gid = lane >> 2, tig = lane & 3;

    unsigned abase = sptr(&Xh[warp * 16 + (lane & 15)][(lane & 16) ? 8 : 0]);
    unsigned bbase[4];
#pragma unroll
    for (int p = 0; p < 4; p++)
        bbase[p] = sptr(&Wn[p * 16 + ((lane & 16) >> 1) + (lane & 7)]
                          [(lane & 8) ? 8 : 0]);

    float acc[8][4];
#pragma unroll
    for (int nt = 0; nt < 8; nt++)
#pragma unroll
        for (int j = 0; j < 4; j++) acc[nt][j] = 0.f;

#pragma unroll
    for (int ks = 0; ks < 4; ks++) {
        unsigned kb2 = ks * 32;
        unsigned a0, a1, a2, a3;
        ldsm4(a0, a1, a2, a3, abase + kb2);
#pragma unroll
        for (int p = 0; p < 4; p++) {
            unsigned b0, b1, b2, b3;
            ldsm4(b0, b1, b2, b3, bbase[p] + kb2);
            mma16816(acc[2 * p][0], acc[2 * p][1], acc[2 * p][2], acc[2 * p][3],
                     a0, a1, a2, a3, b0, b1);
            mma16816(acc[2 * p + 1][0], acc[2 * p + 1][1], acc[2 * p + 1][2], acc[2 * p + 1][3],
                     a0, a1, a2, a3, b2, b3);
        }
    }

    int grow0 = rb + warp * 16 + gid;
    int grow8 = grow0 + 8;
    float ps0 = 0.f, pd0 = 0.f, ps8 = 0.f, pd8 = 0.f;
#pragma unroll
    for (int nt = 0; nt < 8; nt++) {
        int col = nt * 8 + 2 * tig;
        if (grow0 < NN)
            *(__half2*)&g_h16[grow0 * 64 + col] =
                __float22half2_rn(make_float2(acc[nt][0], acc[nt][1]));
        if (grow8 < NN)
            *(__half2*)&g_h16[grow8 * 64 + col] =
                __float22half2_rn(make_float2(acc[nt][2], acc[nt][3]));
        float s0 = ash[col], s1 = ash[col + 1];
        float d0 = adh[col], d1 = adh[col + 1];
        ps0 += acc[nt][0] * s0 + acc[nt][1] * s1;
        pd0 += acc[nt][0] * d0 + acc[nt][1] * d1;
        ps8 += acc[nt][2] * s0 + acc[nt][3] * s1;
        pd8 += acc[nt][2] * d0 + acc[nt][3] * d1;
    }
    ps0 += __shfl_xor_sync(0xffffffffu, ps0, 1);
    ps0 += __shfl_xor_sync(0xffffffffu, ps0, 2);
    pd0 += __shfl_xor_sync(0xffffffffu, pd0, 1);
    pd0 += __shfl_xor_sync(0xffffffffu, pd0, 2);
    ps8 += __shfl_xor_sync(0xffffffffu, ps8, 1);
    ps8 += __shfl_xor_sync(0xffffffffu, ps8, 2);
    pd8 += __shfl_xor_sync(0xffffffffu, pd8, 1);
    pd8 += __shfl_xor_sync(0xffffffffu, pd8, 2);
    if (tig == 0) {
        if (grow0 < NN) { g_es[grow0] = ps0; g_ed[grow0] = pd0; }
        if (grow8 < NN) { g_es[grow8] = ps8; g_ed[grow8] = pd8; }
    }

    float mmax = -3.4e38f;
    if (grow0 < NN) mmax = fmaxf(mmax, ps0);
    if (grow8 < NN) mmax = fmaxf(mmax, ps8);
#pragma unroll
    for (int o = 16; o > 0; o >>= 1)
        mmax = fmaxf(mmax, __shfl_xor_sync(0xffffffffu, mmax, o));
    if (lane == 0) smax[warp] = mmax;
    __syncthreads();
    if (tid == 0) {
        float bm = smax[0];
#pragma unroll
        for (int j = 1; j < 8; j++) bm = fmaxf(bm, smax[j]);
        atomicMax(&g_gmaxu[layer], fenc(bm));
    }
}

// ---- per-edge (src, weight) pairs ----
__global__ void __launch_bounds__(256) k_weight(int layer) {
    int i = blockIdx.x * blockDim.x + threadIdx.x;
    if (i >= ETOT) return;
    float gmax = fdec(g_gmaxu[layer]);
    int2 cd = __ldg(&g_csrd[i]);
    float edd = __ldg(&g_ed[cd.y]);
    float e = __ldg(&g_es[cd.x]) + edd;
    e = (e > 0.f) ? e : 0.2f * e;
    float gm = gmax + edd;
    float m = (gm > 0.f) ? gm : 0.2f * gm;   // >= segment max (lrelu monotone)
    g_sw[i] = make_uint2((unsigned)cd.x, __float_as_uint(__expf(e - m)));
}

// ---- aggregate: warp per node, 2 half-warps, sw prefetch + unroll 8 ----
__global__ void __launch_bounds__(256) k_agg(
    int layer, const float* __restrict__ bias,
    const float4* __restrict__ emb4, float4* __restrict__ out4)
{
    __shared__ float sbias[64];
    int tid = threadIdx.x;
    if (tid < 64) sbias[tid] = bias[tid];
    __syncthreads();

    int lane = tid & 31;
    int n = blockIdx.x * 8 + (tid >> 5);
    if (n >= NN) return;

    int beg = g_rowptr[n];
    int end = g_rowptr[n + 1];

    int half = lane >> 4, hl = lane & 15;
    float denom = 0.f;
    float4 acc = make_float4(0.f, 0.f, 0.f, 0.f);
    const uint2* h2 = (const uint2*)g_h16;

    int k = beg + half;
    // software pipeline: sw pair fetched one iteration ahead
    uint2 p = (k < end) ? __ldg(&g_sw[k]) : make_uint2(0u, 0u);
#pragma unroll 8
    for (; k < end; k += 2) {
        int kn = k + 2;
        uint2 pn = (kn < end) ? __ldg(&g_sw[kn]) : make_uint2(0u, 0u);
        int s = (int)p.x;
        float w = __uint_as_float(p.y);
        denom += w;
        uint2 hv = __ldg(&h2[s * 16 + hl]);  // 4 fp16 elems, 128B/half-warp
        float2 lo = __half22float2(*(__half2*)&hv.x);
        float2 hi = __half22float2(*(__half2*)&hv.y);
        acc.x = fmaf(w, lo.x, acc.x);
        acc.y = fmaf(w, lo.y, acc.y);
        acc.z = fmaf(w, hi.x, acc.z);
        acc.w = fmaf(w, hi.y, acc.w);
        p = pn;
    }
    denom += __shfl_xor_sync(0xffffffffu, denom, 16);
    acc.x += __shfl_xor_sync(0xffffffffu, acc.x, 16);
    acc.y += __shfl_xor_sync(0xffffffffu, acc.y, 16);
    acc.z += __shfl_xor_sync(0xffffffffu, acc.z, 16);
    acc.w += __shfl_xor_sync(0xffffffffu, acc.w, 16);

    if (half == 0) {
        float inv = 1.f / (denom + 1e-16f);
        float4 b4 = ((const float4*)sbias)[hl];
        float4 v;
        v.x = acc.x * inv + b4.x;
        v.y = acc.y * inv + b4.y;
        v.z = acc.z * inv + b4.z;
        v.w = acc.w * inv + b4.w;
        v.x = (v.x > 0.f) ? v.x : expm1f(v.x);
        v.y = (v.y > 0.f) ? v.y : expm1f(v.y);
        v.z = (v.z > 0.f) ? v.z : expm1f(v.z);
        v.w = (v.w > 0.f) ? v.w : expm1f(v.w);

        int base = n * 16 + hl;
        if (layer == 2) {
            // out = (emb + x1 + x2 + x3) / 4   (emb fp32, x1/x2 fp16)
            float4 e4 = emb4[base];
            uint2 u1 = ((const uint2*)g_x1h)[base];
            uint2 u2 = ((const uint2*)g_x2h)[base];
            float2 a0 = __half22float2(*(__half2*)&u1.x);
            float2 a1 = __half22float2(*(__half2*)&u1.y);
            float2 c0 = __half22float2(*(__half2*)&u2.x);
            float2 c1 = __half22float2(*(__half2*)&u2.y);
            float4 o4;
            o4.x = (e4.x + a0.x + c0.x + v.x) * 0.25f;
            o4.y = (e4.y + a0.y + c0.y + v.y) * 0.25f;
            o4.z = (e4.z + a1.x + c1.x + v.z) * 0.25f;
            o4.w = (e4.w + a1.y + c1.y + v.w) * 0.25f;
            out4[base] = o4;
        } else {
            __half2 lo = __float22half2_rn(make_float2(v.x, v.y));
            __half2 hi = __float22half2_rn(make_float2(v.z, v.w));
            uint2* xo = (uint2*)((layer == 0) ? g_x1h : g_x2h);
            xo[base] = make_uint2(*(unsigned*)&lo, *(unsigned*)&hi);
        }
    }
}

extern "C" void kernel_launch(void* const* d_in, const int* in_sizes, int n_in,
                              void* d_out, int out_size) {
    const int*   ei   = (const int*)d_in[0];
    const float* emb  = (const float*)d_in[1];
    const float* W    = (const float*)d_in[2];
    const float* a_s  = (const float*)d_in[3];
    const float* a_d  = (const float*)d_in[4];
    const float* bias = (const float*)d_in[5];
    float* out = (float*)d_out;

    const int* srcs = ei;
    const int* dsts = ei + EE;

    k_emb16<<<(NN * DD / 4 + 255) / 256, 256>>>((const float4*)emb);
    k_count<<<(EE / 4 + 255) / 256, 256>>>(dsts);
    k_bsum<<<NB_SCAN, 256>>>();
    // transform(l0): needs emb16 only; 4th slot so ncu profiles it
    k_transform<<<(NN + 127) / 128, 256>>>(0, W, a_s, a_d);
    k_fillptr<<<NB_SCAN, 256>>>();
    k_fill<<<(ETOT + 255) / 256, 256>>>(srcs, dsts);
    k_weight<<<(ETOT + 255) / 256, 256>>>(0);
    k_agg<<<(NN + 7) / 8, 256>>>(0, bias, (const float4*)emb, (float4*)out);

    for (int l = 1; l < 3; l++) {
        k_transform<<<(NN + 127) / 128, 256>>>(l, W + l * DD * DD,
                                               a_s + l * DD, a_d + l * DD);
        k_weight<<<(ETOT + 255) / 256, 256>>>(l);
        k_agg<<<(NN + 7) / 8, 256>>>(l, bias + l * DD, (const float4*)emb, (float4*)out);
    }
}

// round 14
// speedup vs baseline: 1.0460x; 1.0460x over previous
#include <cuda_runtime.h>
#include <cuda_fp16.h>
#include <math.h>

#define NN 100000
#define DD 64
#define EE 1600000
#define ETOT (EE + NN)
#define NB_SCAN 391   // ceil(NN/256)

// ---- scratch ----
__device__ __half g_h16[NN * DD];   // transformed features (payload, fp16)
__device__ __half g_e16[NN * DD];   // emb in fp16 (GEMM input, layer 0)
__device__ __half g_x1h[NN * DD];   // layer-1 output, fp16
__device__ __half g_x2h[NN * DD];   // layer-2 output, fp16
__device__ float  g_es[NN];
__device__ float  g_ed[NN];
__device__ uint2  g_sw[ETOT];       // per-edge (src, softmax weight)
__device__ int    g_counts[NN];
__device__ int    g_rowptr[NN + 1];
__device__ int    g_cursor[NN];
__device__ int2   g_csrd[ETOT];     // (src, dst) per CSR slot
__device__ int    g_bsum[NB_SCAN];
__device__ unsigned g_gmaxu[3];

// monotone float <-> orderable uint
__device__ __forceinline__ unsigned fenc(float f) {
    unsigned b = __float_as_uint(f);
    return (b & 0x80000000u) ? ~b : (b | 0x80000000u);
}
__device__ __forceinline__ float fdec(unsigned e) {
    return __uint_as_float((e & 0x80000000u) ? (e ^ 0x80000000u) : ~e);
}
__device__ __forceinline__ unsigned sptr(const void* p) {
    return (unsigned)__cvta_generic_to_shared(p);
}

// ---- init: emb -> fp16, counts = 1 (self loop), gmax reset ----
__global__ void k_emb16(const float4* __restrict__ emb4) {
    int i = blockIdx.x * blockDim.x + threadIdx.x;
    if (i < NN * DD / 4) {
        float4 v = emb4[i];
        __half2 lo = __float22half2_rn(make_float2(v.x, v.y));
        __half2 hi = __float22half2_rn(make_float2(v.z, v.w));
        ((uint2*)g_e16)[i] = make_uint2(*(unsigned*)&lo, *(unsigned*)&hi);
    }
    if (i < NN) g_counts[i] = 1;
    if (i < 3) g_gmaxu[i] = 0u;
}

// ---- in-degree count ----
__global__ void k_count(const int* __restrict__ dsts) {
    int i = blockIdx.x * blockDim.x + threadIdx.x;
    if (i >= EE / 4) return;
    int4 d = ((const int4*)dsts)[i];
    atomicAdd(&g_counts[d.x], 1);
    atomicAdd(&g_counts[d.y], 1);
    atomicAdd(&g_counts[d.z], 1);
    atomicAdd(&g_counts[d.w], 1);
}

// ---- block sums of counts ----
__global__ void __launch_bounds__(256) k_bsum() {
    __shared__ int sh[256];
    int t = threadIdx.x;
    int i = blockIdx.x * 256 + t;
    sh[t] = (i < NN) ? g_counts[i] : 0;
    __syncthreads();
    for (int o = 128; o > 0; o >>= 1) {
        if (t < o) sh[t] += sh[t + o];
        __syncthreads();
    }
    if (t == 0) g_bsum[blockIdx.x] = sh[0];
}

// ---- rowptr: per-block offset + local scan ----
__global__ void __launch_bounds__(256) k_fillptr() {
    __shared__ int sh[256];
    __shared__ int wsum[8];
    __shared__ int s_off;
    int t = threadIdx.x, b = blockIdx.x;
    int part = 0;
    for (int j = t; j < b; j += 256) part += g_bsum[j];
    sh[t] = part;
    __syncthreads();
    for (int o = 128; o > 0; o >>= 1) {
        if (t < o) sh[t] += sh[t + o];
        __syncthreads();
    }
    if (t == 0) s_off = sh[0];
    __syncthreads();

    int i = b * 256 + t;
    int c = (i < NN) ? g_counts[i] : 0;
    int lane = t & 31, w = t >> 5;
    int v = c;
#pragma unroll
    for (int o = 1; o < 32; o <<= 1) {
        int u = __shfl_up_sync(0xffffffffu, v, o);
        if (lane >= o) v += u;
    }
    if (lane == 31) wsum[w] = v;
    __syncthreads();
    if (t == 0) {
        int run = 0;
#pragma unroll
        for (int j = 0; j < 8; j++) { int tmp = wsum[j]; wsum[j] = run; run += tmp; }
    }
    __syncthreads();
    int excl = s_off + wsum[w] + v - c;
    if (i < NN) {
        g_rowptr[i] = excl;
        g_cursor[i] = excl;
        if (i == NN - 1) g_rowptr[NN] = excl + c;
    }
}

// ---- scatter (src,dst) into dst buckets (+ self loops), scalar ----
__global__ void k_fill(const int* __restrict__ srcs, const int* __restrict__ dsts) {
    int i = blockIdx.x * blockDim.x + threadIdx.x;
    if (i >= ETOT) return;
    int s, d;
    if (i < EE) { s = srcs[i]; d = dsts[i]; }
    else        { s = d = i - EE; }
    int pos = atomicAdd(&g_cursor[d], 1);
    g_csrd[pos] = make_int2(s, d);
}

// ---- HMMA helpers ----
__device__ __forceinline__ void mma16816(
    float& c0, float& c1, float& c2, float& c3,
    unsigned a0, unsigned a1, unsigned a2, unsigned a3,
    unsigned b0, unsigned b1)
{
    asm volatile(
        "mma.sync.aligned.m16n8k16.row.col.f32.f16.f16.f32 "
        "{%0,%1,%2,%3}, {%4,%5,%6,%7}, {%8,%9}, {%0,%1,%2,%3};"
        : "+f"(c0), "+f"(c1), "+f"(c2), "+f"(c3)
        : "r"(a0), "r"(a1), "r"(a2), "r"(a3), "r"(b0), "r"(b1));
}
__device__ __forceinline__ void ldsm4(
    unsigned& r0, unsigned& r1, unsigned& r2, unsigned& r3, unsigned addr)
{
    asm volatile(
        "ldmatrix.sync.aligned.m8n8.x4.shared.b16 {%0,%1,%2,%3}, [%4];"
        : "=r"(r0), "=r"(r1), "=r"(r2), "=r"(r3) : "r"(addr));
}

// ---- transform: h = x@W via HMMA; fp16 in/out; es/ed; fused block-max ----
#define XPAD 72
__global__ void __launch_bounds__(256) k_transform(
    int layer, const float* __restrict__ W,
    const float* __restrict__ a_s, const float* __restrict__ a_d)
{
    __shared__ __half Xh[128][XPAD];
    __shared__ __half Wn[64][XPAD];   // Wn[n][k] = W[k][n]
    __shared__ float ash[64];
    __shared__ float adh[64];
    __shared__ float smax[8];
    const __half* x = (layer == 0) ? g_e16 : (layer == 1 ? g_x1h : g_x2h);
    int tid = threadIdx.x;
    int rb = blockIdx.x * 128;

    const float4* Wg4 = (const float4*)W;
#pragma unroll
    for (int idx = tid; idx < 1024; idx += 256) {
        int k = idx >> 4, n4 = (idx & 15) << 2;
        float4 w = Wg4[idx];
        Wn[n4 + 0][k] = __float2half(w.x);
        Wn[n4 + 1][k] = __float2half(w.y);
        Wn[n4 + 2][k] = __float2half(w.z);
        Wn[n4 + 3][k] = __float2half(w.w);
    }
    if (tid < 64) { ash[tid] = a_s[tid]; adh[tid] = a_d[tid]; }

    const uint4* Xg = (const uint4*)x;
#pragma unroll
    for (int idx = tid; idx < 1024; idx += 256) {
        int r = idx >> 3, c8 = idx & 7;
        uint4 v = (rb + r < NN) ? Xg[(rb + r) * 8 + c8]
                                : make_uint4(0u, 0u, 0u, 0u);
        *(uint4*)&Xh[r][c8 * 8] = v;
    }
    __syncthreads();

    int warp = tid >> 5, lane = tid & 31;
    int gid = lane >> 2, tig = lane & 3;

    unsigned abase = sptr(&Xh[warp * 16 + (lane & 15)][(lane & 16) ? 8 : 0]);
    unsigned bbase[4];
#pragma unroll
    for (int p = 0; p < 4; p++)
        bbase[p] = sptr(&Wn[p * 16 + ((lane & 16) >> 1) + (lane & 7)]
                          [(lane & 8) ? 8 : 0]);

    float acc[8][4];
#pragma unroll
    for (int nt = 0; nt < 8; nt++)
#pragma unroll
        for (int j = 0; j < 4; j++) acc[nt][j] = 0.f;

#pragma unroll
    for (int ks = 0; ks < 4; ks++) {
        unsigned kb2 = ks * 32;
        unsigned a0, a1, a2, a3;
        ldsm4(a0, a1, a2, a3, abase + kb2);
#pragma unroll
        for (int p = 0; p < 4; p++) {
            unsigned b0, b1, b2, b3;
            ldsm4(b0, b1, b2, b3, bbase[p] + kb2);
            mma16816(acc[2 * p][0], acc[2 * p][1], acc[2 * p][2], acc[2 * p][3],
                     a0, a1, a2, a3, b0, b1);
            mma16816(acc[2 * p + 1][0], acc[2 * p + 1][1], acc[2 * p + 1][2], acc[2 * p + 1][3],
                     a0, a1, a2, a3, b2, b3);
        }
    }

    int grow0 = rb + warp * 16 + gid;
    int grow8 = grow0 + 8;
    float ps0 = 0.f, pd0 = 0.f, ps8 = 0.f, pd8 = 0.f;
#pragma unroll
    for (int nt = 0; nt < 8; nt++) {
        int col = nt * 8 + 2 * tig;
        if (grow0 < NN)
            *(__half2*)&g_h16[grow0 * 64 + col] =
                __float22half2_rn(make_float2(acc[nt][0], acc[nt][1]));
        if (grow8 < NN)
            *(__half2*)&g_h16[grow8 * 64 + col] =
                __float22half2_rn(make_float2(acc[nt][2], acc[nt][3]));
        float s0 = ash[col], s1 = ash[col + 1];
        float d0 = adh[col], d1 = adh[col + 1];
        ps0 += acc[nt][0] * s0 + acc[nt][1] * s1;
        pd0 += acc[nt][0] * d0 + acc[nt][1] * d1;
        ps8 += acc[nt][2] * s0 + acc[nt][3] * s1;
        pd8 += acc[nt][2] * d0 + acc[nt][3] * d1;
    }
    ps0 += __shfl_xor_sync(0xffffffffu, ps0, 1);
    ps0 += __shfl_xor_sync(0xffffffffu, ps0, 2);
    pd0 += __shfl_xor_sync(0xffffffffu, pd0, 1);
    pd0 += __shfl_xor_sync(0xffffffffu, pd0, 2);
    ps8 += __shfl_xor_sync(0xffffffffu, ps8, 1);
    ps8 += __shfl_xor_sync(0xffffffffu, ps8, 2);
    pd8 += __shfl_xor_sync(0xffffffffu, pd8, 1);
    pd8 += __shfl_xor_sync(0xffffffffu, pd8, 2);
    if (tig == 0) {
        if (grow0 < NN) { g_es[grow0] = ps0; g_ed[grow0] = pd0; }
        if (grow8 < NN) { g_es[grow8] = ps8; g_ed[grow8] = pd8; }
    }

    float mmax = -3.4e38f;
    if (grow0 < NN) mmax = fmaxf(mmax, ps0);
    if (grow8 < NN) mmax = fmaxf(mmax, ps8);
#pragma unroll
    for (int o = 16; o > 0; o >>= 1)
        mmax = fmaxf(mmax, __shfl_xor_sync(0xffffffffu, mmax, o));
    if (lane == 0) smax[warp] = mmax;
    __syncthreads();
    if (tid == 0) {
        float bm = smax[0];
#pragma unroll
        for (int j = 1; j < 8; j++) bm = fmaxf(bm, smax[j]);
        atomicMax(&g_gmaxu[layer], fenc(bm));
    }
}

// ---- per-edge (src, weight) pairs ----
__global__ void __launch_bounds__(256) k_weight(int layer) {
    int i = blockIdx.x * blockDim.x + threadIdx.x;
    if (i >= ETOT) return;
    float gmax = fdec(g_gmaxu[layer]);
    int2 cd = __ldg(&g_csrd[i]);
    float edd = __ldg(&g_ed[cd.y]);
    float e = __ldg(&g_es[cd.x]) + edd;
    e = (e > 0.f) ? e : 0.2f * e;
    float gm = gmax + edd;
    float m = (gm > 0.f) ? gm : 0.2f * gm;   // >= segment max (lrelu monotone)
    g_sw[i] = make_uint2((unsigned)cd.x, __float_as_uint(__expf(e - m)));
}

// ---- aggregate: warp per node, 2 half-warps, register-staged sw batches ----
// Lane (half*16 + j) stages edge (beg + b + half + 2j); inner loop gets
// (src,w) via shfl (no memory latency in chain), h-gathers unrolled x4.
// OOB lanes stage (0, w=0) -> padded iterations contribute exactly zero.
__global__ void __launch_bounds__(256) k_agg(
    int layer, const float* __restrict__ bias,
    const float4* __restrict__ emb4, float4* __restrict__ out4)
{
    __shared__ float sbias[64];
    int tid = threadIdx.x;
    if (tid < 64) sbias[tid] = bias[tid];
    __syncthreads();

    int lane = tid & 31;
    int n = blockIdx.x * 8 + (tid >> 5);
    if (n >= NN) return;

    int beg = g_rowptr[n];
    int end = g_rowptr[n + 1];
    int tot = end - beg;                 // warp-uniform

    int half = lane >> 4, hl = lane & 15;
    float denom = 0.f;
    float4 acc = make_float4(0.f, 0.f, 0.f, 0.f);
    const uint2* h2 = (const uint2*)g_h16;

    for (int b = 0; b < tot; b += 32) {
        // stage: one coalesced 8B load per lane (256B/warp, contiguous)
        int my = beg + b + half + 2 * hl;
        uint2 pb = (my < end) ? __ldg(&g_sw[my]) : make_uint2(0u, 0u);
        int rem = tot - b;
        int jmax = (rem < 32) ? ((rem + 1) >> 1) : 16;   // warp-uniform
#pragma unroll 4
        for (int j = 0; j < jmax; j++) {
            int srcl = (half << 4) + j;
            int s = __shfl_sync(0xffffffffu, (int)pb.x, srcl);
            float w = __uint_as_float(__shfl_sync(0xffffffffu, pb.y, srcl));
            denom += w;
            uint2 hv = __ldg(&h2[s * 16 + hl]);
            float2 lo = __half22float2(*(__half2*)&hv.x);
            float2 hi = __half22float2(*(__half2*)&hv.y);
            acc.x = fmaf(w, lo.x, acc.x);
            acc.y = fmaf(w, lo.y, acc.y);
            acc.z = fmaf(w, hi.x, acc.z);
            acc.w = fmaf(w, hi.y, acc.w);
        }
    }
    denom += __shfl_xor_sync(0xffffffffu, denom, 16);
    acc.x += __shfl_xor_sync(0xffffffffu, acc.x, 16);
    acc.y += __shfl_xor_sync(0xffffffffu, acc.y, 16);
    acc.z += __shfl_xor_sync(0xffffffffu, acc.z, 16);
    acc.w += __shfl_xor_sync(0xffffffffu, acc.w, 16);

    if (half == 0) {
        float inv = 1.f / (denom + 1e-16f);
        float4 b4 = ((const float4*)sbias)[hl];
        float4 v;
        v.x = acc.x * inv + b4.x;
        v.y = acc.y * inv + b4.y;
        v.z = acc.z * inv + b4.z;
        v.w = acc.w * inv + b4.w;
        v.x = (v.x > 0.f) ? v.x : expm1f(v.x);
        v.y = (v.y > 0.f) ? v.y : expm1f(v.y);
        v.z = (v.z > 0.f) ? v.z : expm1f(v.z);
        v.w = (v.w > 0.f) ? v.w : expm1f(v.w);

        int base = n * 16 + hl;
        if (layer == 2) {
            // out = (emb + x1 + x2 + x3) / 4   (emb fp32, x1/x2 fp16)
            float4 e4 = emb4[base];
            uint2 u1 = ((const uint2*)g_x1h)[base];
            uint2 u2 = ((const uint2*)g_x2h)[base];
            float2 a0 = __half22float2(*(__half2*)&u1.x);
            float2 a1 = __half22float2(*(__half2*)&u1.y);
            float2 c0 = __half22float2(*(__half2*)&u2.x);
            float2 c1 = __half22float2(*(__half2*)&u2.y);
            float4 o4;
            o4.x = (e4.x + a0.x + c0.x + v.x) * 0.25f;
            o4.y = (e4.y + a0.y + c0.y + v.y) * 0.25f;
            o4.z = (e4.z + a1.x + c1.x + v.z) * 0.25f;
            o4.w = (e4.w + a1.y + c1.y + v.w) * 0.25f;
            out4[base] = o4;
        } else {
            __half2 lo = __float22half2_rn(make_float2(v.x, v.y));
            __half2 hi = __float22half2_rn(make_float2(v.z, v.w));
            uint2* xo = (uint2*)((layer == 0) ? g_x1h : g_x2h);
            xo[base] = make_uint2(*(unsigned*)&lo, *(unsigned*)&hi);
        }
    }
}

extern "C" void kernel_launch(void* const* d_in, const int* in_sizes, int n_in,
                              void* d_out, int out_size) {
    const int*   ei   = (const int*)d_in[0];
    const float* emb  = (const float*)d_in[1];
    const float* W    = (const float*)d_in[2];
    const float* a_s  = (const float*)d_in[3];
    const float* a_d  = (const float*)d_in[4];
    const float* bias = (const float*)d_in[5];
    float* out = (float*)d_out;

    const int* srcs = ei;
    const int* dsts = ei + EE;

    k_emb16<<<(NN * DD / 4 + 255) / 256, 256>>>((const float4*)emb);
    k_count<<<(EE / 4 + 255) / 256, 256>>>(dsts);
    k_bsum<<<NB_SCAN, 256>>>();
    // transform(l0): needs emb16 only; 4th slot so ncu profiles it
    k_transform<<<(NN + 127) / 128, 256>>>(0, W, a_s, a_d);
    k_fillptr<<<NB_SCAN, 256>>>();
    k_fill<<<(ETOT + 255) / 256, 256>>>(srcs, dsts);
    k_weight<<<(ETOT + 255) / 256, 256>>>(0);
    k_agg<<<(NN + 7) / 8, 256>>>(0, bias, (const float4*)emb, (float4*)out);

    for (int l = 1; l < 3; l++) {
        k_transform<<<(NN + 127) / 128, 256>>>(l, W + l * DD * DD,
                                               a_s + l * DD, a_d + l * DD);
        k_weight<<<(ETOT + 255) / 256, 256>>>(l);
        k_agg<<<(NN + 7) / 8, 256>>>(l, bias + l * DD, (const float4*)emb, (float4*)out);
    }
}

// round 15
// speedup vs baseline: 1.1105x; 1.0616x over previous
#include <cuda_runtime.h>
#include <cuda_fp16.h>
#include <math.h>

#define NN 100000
#define DD 64
#define EE 1600000
#define ETOT (EE + NN)
#define NB_SCAN 391   // ceil(NN/256)

// ---- scratch ----
__device__ __half g_h16[NN * DD];   // transformed features (payload, fp16)
__device__ __half g_e16[NN * DD];   // emb in fp16 (GEMM input, layer 0)
__device__ __half g_x1h[NN * DD];   // layer-1 output, fp16
__device__ __half g_x2h[NN * DD];   // layer-2 output, fp16
__device__ float  g_es[NN];
__device__ float  g_ed[NN];
__device__ uint2  g_sw[ETOT];       // per-edge (src, softmax weight)
__device__ int    g_counts[NN];
__device__ int    g_rowptr[NN + 1];
__device__ int    g_cursor[NN];
__device__ int2   g_csrd[ETOT];     // (src, dst) per CSR slot
__device__ int    g_bsum[NB_SCAN];
__device__ unsigned g_gmaxu[3];

// monotone float <-> orderable uint
__device__ __forceinline__ unsigned fenc(float f) {
    unsigned b = __float_as_uint(f);
    return (b & 0x80000000u) ? ~b : (b | 0x80000000u);
}
__device__ __forceinline__ float fdec(unsigned e) {
    return __uint_as_float((e & 0x80000000u) ? (e ^ 0x80000000u) : ~e);
}
__device__ __forceinline__ unsigned sptr(const void* p) {
    return (unsigned)__cvta_generic_to_shared(p);
}

// ---- compute branch init: emb -> fp16 + gmax reset ----
__global__ void k_emb16(const float4* __restrict__ emb4) {
    int i = blockIdx.x * blockDim.x + threadIdx.x;
    if (i < NN * DD / 4) {
        float4 v = emb4[i];
        __half2 lo = __float22half2_rn(make_float2(v.x, v.y));
        __half2 hi = __float22half2_rn(make_float2(v.z, v.w));
        ((uint2*)g_e16)[i] = make_uint2(*(unsigned*)&lo, *(unsigned*)&hi);
    }
    if (i < 3) g_gmaxu[i] = 0u;
}

// ---- CSR branch init: counts = 1 (self loop) ----
__global__ void k_init2() {
    int i = blockIdx.x * blockDim.x + threadIdx.x;
    if (i < NN) g_counts[i] = 1;
}

// ---- in-degree count ----
__global__ void k_count(const int* __restrict__ dsts) {
    int i = blockIdx.x * blockDim.x + threadIdx.x;
    if (i >= EE / 4) return;
    int4 d = ((const int4*)dsts)[i];
    atomicAdd(&g_counts[d.x], 1);
    atomicAdd(&g_counts[d.y], 1);
    atomicAdd(&g_counts[d.z], 1);
    atomicAdd(&g_counts[d.w], 1);
}

// ---- block sums of counts ----
__global__ void __launch_bounds__(256) k_bsum() {
    __shared__ int sh[256];
    int t = threadIdx.x;
    int i = blockIdx.x * 256 + t;
    sh[t] = (i < NN) ? g_counts[i] : 0;
    __syncthreads();
    for (int o = 128; o > 0; o >>= 1) {
        if (t < o) sh[t] += sh[t + o];
        __syncthreads();
    }
    if (t == 0) g_bsum[blockIdx.x] = sh[0];
}

// ---- rowptr: per-block offset + local scan ----
__global__ void __launch_bounds__(256) k_fillptr() {
    __shared__ int sh[256];
    __shared__ int wsum[8];
    __shared__ int s_off;
    int t = threadIdx.x, b = blockIdx.x;
    int part = 0;
    for (int j = t; j < b; j += 256) part += g_bsum[j];
    sh[t] = part;
    __syncthreads();
    for (int o = 128; o > 0; o >>= 1) {
        if (t < o) sh[t] += sh[t + o];
        __syncthreads();
    }
    if (t == 0) s_off = sh[0];
    __syncthreads();

    int i = b * 256 + t;
    int c = (i < NN) ? g_counts[i] : 0;
    int lane = t & 31, w = t >> 5;
    int v = c;
#pragma unroll
    for (int o = 1; o < 32; o <<= 1) {
        int u = __shfl_up_sync(0xffffffffu, v, o);
        if (lane >= o) v += u;
    }
    if (lane == 31) wsum[w] = v;
    __syncthreads();
    if (t == 0) {
        int run = 0;
#pragma unroll
        for (int j = 0; j < 8; j++) { int tmp = wsum[j]; wsum[j] = run; run += tmp; }
    }
    __syncthreads();
    int excl = s_off + wsum[w] + v - c;
    if (i < NN) {
        g_rowptr[i] = excl;
        g_cursor[i] = excl;
        if (i == NN - 1) g_rowptr[NN] = excl + c;
    }
}

// ---- scatter (src,dst) into dst buckets (+ self loops), scalar ----
__global__ void k_fill(const int* __restrict__ srcs, const int* __restrict__ dsts) {
    int i = blockIdx.x * blockDim.x + threadIdx.x;
    if (i >= ETOT) return;
    int s, d;
    if (i < EE) { s = srcs[i]; d = dsts[i]; }
    else        { s = d = i - EE; }
    int pos = atomicAdd(&g_cursor[d], 1);
    g_csrd[pos] = make_int2(s, d);
}

// ---- HMMA helpers ----
__device__ __forceinline__ void mma16816(
    float& c0, float& c1, float& c2, float& c3,
    unsigned a0, unsigned a1, unsigned a2, unsigned a3,
    unsigned b0, unsigned b1)
{
    asm volatile(
        "mma.sync.aligned.m16n8k16.row.col.f32.f16.f16.f32 "
        "{%0,%1,%2,%3}, {%4,%5,%6,%7}, {%8,%9}, {%0,%1,%2,%3};"
        : "+f"(c0), "+f"(c1), "+f"(c2), "+f"(c3)
        : "r"(a0), "r"(a1), "r"(a2), "r"(a3), "r"(b0), "r"(b1));
}
__device__ __forceinline__ void ldsm4(
    unsigned& r0, unsigned& r1, unsigned& r2, unsigned& r3, unsigned addr)
{
    asm volatile(
        "ldmatrix.sync.aligned.m8n8.x4.shared.b16 {%0,%1,%2,%3}, [%4];"
        : "=r"(r0), "=r"(r1), "=r"(r2), "=r"(r3) : "r"(addr));
}

// ---- transform: h = x@W via HMMA; fp16 in/out; es/ed; fused block-max ----
#define XPAD 72
__global__ void __launch_bounds__(256) k_transform(
    int layer, const float* __restrict__ W,
    const float* __restrict__ a_s, const float* __restrict__ a_d)
{
    __shared__ __half Xh[128][XPAD];
    __shared__ __half Wn[64][XPAD];   // Wn[n][k] = W[k][n]
    __shared__ float ash[64];
    __shared__ float adh[64];
    __shared__ float smax[8];
    const __half* x = (layer == 0) ? g_e16 : (layer == 1 ? g_x1h : g_x2h);
    int tid = threadIdx.x;
    int rb = blockIdx.x * 128;

    const float4* Wg4 = (const float4*)W;
#pragma unroll
    for (int idx = tid; idx < 1024; idx += 256) {
        int k = idx >> 4, n4 = (idx & 15) << 2;
        float4 w = Wg4[idx];
        Wn[n4 + 0][k] = __float2half(w.x);
        Wn[n4 + 1][k] = __float2half(w.y);
        Wn[n4 + 2][k] = __float2half(w.z);
        Wn[n4 + 3][k] = __float2half(w.w);
    }
    if (tid < 64) { ash[tid] = a_s[tid]; adh[tid] = a_d[tid]; }

    const uint4* Xg = (const uint4*)x;
#pragma unroll
    for (int idx = tid; idx < 1024; idx += 256) {
        int r = idx >> 3, c8 = idx & 7;
        uint4 v = (rb + r < NN) ? Xg[(rb + r) * 8 + c8]
                                : make_uint4(0u, 0u, 0u, 0u);
        *(uint4*)&Xh[r][c8 * 8] = v;
    }
    __syncthreads();

    int warp = tid >> 5, lane = tid & 31;
    int gid = lane >> 2, tig = lane & 3;

    unsigned abase = sptr(&Xh[warp * 16 + (lane & 15)][(lane & 16) ? 8 : 0]);
    unsigned bbase[4];
#pragma unroll
    for (int p = 0; p < 4; p++)
        bbase[p] = sptr(&Wn[p * 16 + ((lane & 16) >> 1) + (lane & 7)]
                          [(lane & 8) ? 8 : 0]);

    float acc[8][4];
#pragma unroll
    for (int nt = 0; nt < 8; nt++)
#pragma unroll
        for (int j = 0; j < 4; j++) acc[nt][j] = 0.f;

#pragma unroll
    for (int ks = 0; ks < 4; ks++) {
        unsigned kb2 = ks * 32;
        unsigned a0, a1, a2, a3;
        ldsm4(a0, a1, a2, a3, abase + kb2);
#pragma unroll
        for (int p = 0; p < 4; p++) {
            unsigned b0, b1, b2, b3;
            ldsm4(b0, b1, b2, b3, bbase[p] + kb2);
            mma16816(acc[2 * p][0], acc[2 * p][1], acc[2 * p][2], acc[2 * p][3],
                     a0, a1, a2, a3, b0, b1);
            mma16816(acc[2 * p + 1][0], acc[2 * p + 1][1], acc[2 * p + 1][2], acc[2 * p + 1][3],
                     a0, a1, a2, a3, b2, b3);
        }
    }

    int grow0 = rb + warp * 16 + gid;
    int grow8 = grow0 + 8;
    float ps0 = 0.f, pd0 = 0.f, ps8 = 0.f, pd8 = 0.f;
#pragma unroll
    for (int nt = 0; nt < 8; nt++) {
        int col = nt * 8 + 2 * tig;
        if (grow0 < NN)
            *(__half2*)&g_h16[grow0 * 64 + col] =
                __float22half2_rn(make_float2(acc[nt][0], acc[nt][1]));
        if (grow8 < NN)
            *(__half2*)&g_h16[grow8 * 64 + col] =
                __float22half2_rn(make_float2(acc[nt][2], acc[nt][3]));
        float s0 = ash[col], s1 = ash[col + 1];
        float d0 = adh[col], d1 = adh[col + 1];
        ps0 += acc[nt][0] * s0 + acc[nt][1] * s1;
        pd0 += acc[nt][0] * d0 + acc[nt][1] * d1;
        ps8 += acc[nt][2] * s0 + acc[nt][3] * s1;
        pd8 += acc[nt][2] * d0 + acc[nt][3] * d1;
    }
    ps0 += __shfl_xor_sync(0xffffffffu, ps0, 1);
    ps0 += __shfl_xor_sync(0xffffffffu, ps0, 2);
    pd0 += __shfl_xor_sync(0xffffffffu, pd0, 1);
    pd0 += __shfl_xor_sync(0xffffffffu, pd0, 2);
    ps8 += __shfl_xor_sync(0xffffffffu, ps8, 1);
    ps8 += __shfl_xor_sync(0xffffffffu, ps8, 2);
    pd8 += __shfl_xor_sync(0xffffffffu, pd8, 1);
    pd8 += __shfl_xor_sync(0xffffffffu, pd8, 2);
    if (tig == 0) {
        if (grow0 < NN) { g_es[grow0] = ps0; g_ed[grow0] = pd0; }
        if (grow8 < NN) { g_es[grow8] = ps8; g_ed[grow8] = pd8; }
    }

    float mmax = -3.4e38f;
    if (grow0 < NN) mmax = fmaxf(mmax, ps0);
    if (grow8 < NN) mmax = fmaxf(mmax, ps8);
#pragma unroll
    for (int o = 16; o > 0; o >>= 1)
        mmax = fmaxf(mmax, __shfl_xor_sync(0xffffffffu, mmax, o));
    if (lane == 0) smax[warp] = mmax;
    __syncthreads();
    if (tid == 0) {
        float bm = smax[0];
#pragma unroll
        for (int j = 1; j < 8; j++) bm = fmaxf(bm, smax[j]);
        atomicMax(&g_gmaxu[layer], fenc(bm));
    }
}

// ---- per-edge (src, weight) pairs ----
__global__ void __launch_bounds__(256) k_weight(int layer) {
    int i = blockIdx.x * blockDim.x + threadIdx.x;
    if (i >= ETOT) return;
    float gmax = fdec(g_gmaxu[layer]);
    int2 cd = __ldg(&g_csrd[i]);
    float edd = __ldg(&g_ed[cd.y]);
    float e = __ldg(&g_es[cd.x]) + edd;
    e = (e > 0.f) ? e : 0.2f * e;
    float gm = gmax + edd;
    float m = (gm > 0.f) ? gm : 0.2f * gm;   // >= segment max (lrelu monotone)
    g_sw[i] = make_uint2((unsigned)cd.x, __float_as_uint(__expf(e - m)));
}

// ---- aggregate: warp per node, 2 half-warps (R10-best geometry) ----
__global__ void __launch_bounds__(256) k_agg(
    int layer, const float* __restrict__ bias,
    const float4* __restrict__ emb4, float4* __restrict__ out4)
{
    __shared__ float sbias[64];
    int tid = threadIdx.x;
    if (tid < 64) sbias[tid] = bias[tid];
    __syncthreads();

    int lane = tid & 31;
    int n = blockIdx.x * 8 + (tid >> 5);
    if (n >= NN) return;

    int beg = g_rowptr[n];
    int end = g_rowptr[n + 1];

    int half = lane >> 4, hl = lane & 15;
    float denom = 0.f;
    float4 acc = make_float4(0.f, 0.f, 0.f, 0.f);
    const uint2* h2 = (const uint2*)g_h16;

#pragma unroll 4
    for (int k = beg + half; k < end; k += 2) {
        uint2 p = __ldg(&g_sw[k]);           // (src, w) in one 8B load
        int s = (int)p.x;
        float w = __uint_as_float(p.y);
        denom += w;
        uint2 hv = __ldg(&h2[s * 16 + hl]);  // 4 fp16 elems, 128B/half-warp
        float2 lo = __half22float2(*(__half2*)&hv.x);
        float2 hi = __half22float2(*(__half2*)&hv.y);
        acc.x = fmaf(w, lo.x, acc.x);
        acc.y = fmaf(w, lo.y, acc.y);
        acc.z = fmaf(w, hi.x, acc.z);
        acc.w = fmaf(w, hi.y, acc.w);
    }
    denom += __shfl_xor_sync(0xffffffffu, denom, 16);
    acc.x += __shfl_xor_sync(0xffffffffu, acc.x, 16);
    acc.y += __shfl_xor_sync(0xffffffffu, acc.y, 16);
    acc.z += __shfl_xor_sync(0xffffffffu, acc.z, 16);
    acc.w += __shfl_xor_sync(0xffffffffu, acc.w, 16);

    if (half == 0) {
        float inv = 1.f / (denom + 1e-16f);
        float4 b4 = ((const float4*)sbias)[hl];
        float4 v;
        v.x = acc.x * inv + b4.x;
        v.y = acc.y * inv + b4.y;
        v.z = acc.z * inv + b4.z;
        v.w = acc.w * inv + b4.w;
        v.x = (v.x > 0.f) ? v.x : expm1f(v.x);
        v.y = (v.y > 0.f) ? v.y : expm1f(v.y);
        v.z = (v.z > 0.f) ? v.z : expm1f(v.z);
        v.w = (v.w > 0.f) ? v.w : expm1f(v.w);

        int base = n * 16 + hl;
        if (layer == 2) {
            // out = (emb + x1 + x2 + x3) / 4   (emb fp32, x1/x2 fp16)
            float4 e4 = emb4[base];
            uint2 u1 = ((const uint2*)g_x1h)[base];
            uint2 u2 = ((const uint2*)g_x2h)[base];
            float2 a0 = __half22float2(*(__half2*)&u1.x);
            float2 a1 = __half22float2(*(__half2*)&u1.y);
            float2 c0 = __half22float2(*(__half2*)&u2.x);
            float2 c1 = __half22float2(*(__half2*)&u2.y);
            float4 o4;
            o4.x = (e4.x + a0.x + c0.x + v.x) * 0.25f;
            o4.y = (e4.y + a0.y + c0.y + v.y) * 0.25f;
            o4.z = (e4.z + a1.x + c1.x + v.z) * 0.25f;
            o4.w = (e4.w + a1.y + c1.y + v.w) * 0.25f;
            out4[base] = o4;
        } else {
            __half2 lo = __float22half2_rn(make_float2(v.x, v.y));
            __half2 hi = __float22half2_rn(make_float2(v.z, v.w));
            uint2* xo = (uint2*)((layer == 0) ? g_x1h : g_x2h);
            xo[base] = make_uint2(*(unsigned*)&lo, *(unsigned*)&hi);
        }
    }
}

extern "C" void kernel_launch(void* const* d_in, const int* in_sizes, int n_in,
                              void* d_out, int out_size) {
    const int*   ei   = (const int*)d_in[0];
    const float* emb  = (const float*)d_in[1];
    const float* W    = (const float*)d_in[2];
    const float* a_s  = (const float*)d_in[3];
    const float* a_d  = (const float*)d_in[4];
    const float* bias = (const float*)d_in[5];
    float* out = (float*)d_out;

    const int* srcs = ei;
    const int* dsts = ei + EE;

    // Fork/join resources: created ONCE on the first (non-capture) call.
    static cudaStream_t s2 = nullptr;
    static cudaEvent_t evFork = nullptr, evJoin = nullptr;
    if (s2 == nullptr) {
        cudaStreamCreateWithFlags(&s2, cudaStreamNonBlocking);
        cudaEventCreateWithFlags(&evFork, cudaEventDisableTiming);
        cudaEventCreateWithFlags(&evJoin, cudaEventDisableTiming);
    }

    // fork: CSR build on s2, feature pipeline on default stream
    cudaEventRecord(evFork, 0);
    cudaStreamWaitEvent(s2, evFork, 0);

    // compute branch (default stream)
    k_emb16<<<(NN * DD / 4 + 255) / 256, 256>>>((const float4*)emb);
    k_transform<<<(NN + 127) / 128, 256>>>(0, W, a_s, a_d);

    // CSR branch (s2)
    k_init2<<<(NN + 255) / 256, 256, 0, s2>>>();
    k_count<<<(EE / 4 + 255) / 256, 256, 0, s2>>>(dsts);
    k_bsum<<<NB_SCAN, 256, 0, s2>>>();
    k_fillptr<<<NB_SCAN, 256, 0, s2>>>();
    k_fill<<<(ETOT + 255) / 256, 256, 0, s2>>>(srcs, dsts);
    cudaEventRecord(evJoin, s2);

    // join
    cudaStreamWaitEvent(0, evJoin, 0);

    k_weight<<<(ETOT + 255) / 256, 256>>>(0);
    k_agg<<<(NN + 7) / 8, 256>>>(0, bias, (const float4*)emb, (float4*)out);

    for (int l = 1; l < 3; l++) {
        k_transform<<<(NN + 127) / 128, 256>>>(l, W + l * DD * DD,
                                               a_s + l * DD, a_d + l * DD);
        k_weight<<<(ETOT + 255) / 256, 256>>>(l);
        k_agg<<<(NN + 7) / 8, 256>>>(l, bias + l * DD, (const float4*)emb, (float4*)out);
    }
}